// round 5
// baseline (speedup 1.0000x reference)
#include <cuda_runtime.h>
#include <cuda_bf16.h>

// MergedEmbeddingBag: weights [T,N,D] f32, indices [T,TOTAL] i32, offsets [T,B] i32
// out [T,B,D] f32, sum pooling. T=8, N=100000, D=128, B=16384, L=20.
//
// R5: best-known schedule (R2: warp-per-bag, float4 gathers, shfl-distributed
// indices, no smem/barriers) +
//   - ld.global.nc.L1::no_allocate for gathers (random over 51MB/table: ~0% L1
//     hit rate; skip L1 fill, keep idx/offset lines in L1)
//   - st.global.cs for output (evict-first: don't displace weight rows in L2)
// Theory: kernel sits at the chip LTS cap (~12.2 TB/s @NAT); this round is the
// falsification test of that floor.

#define EB_T 8
#define EB_N 100000
#define EB_D 128
#define EB_B 16384
#define EB_LOG2_B 14
#define FULLMASK 0xffffffffu

__device__ __forceinline__ float4 ldg_na_v4(const float4* p)
{
    float4 v;
    asm volatile("ld.global.nc.L1::no_allocate.v4.f32 {%0,%1,%2,%3}, [%4];"
                 : "=f"(v.x), "=f"(v.y), "=f"(v.z), "=f"(v.w)
                 : "l"(p));
    return v;
}

__global__ void __launch_bounds__(256, 4)
merged_embeddingbag_warp_kernel(const float* __restrict__ weights,
                                const int* __restrict__ indices,
                                const int* __restrict__ offsets,
                                float* __restrict__ out,
                                int total_per_table)
{
    const int gw   = blockIdx.x * (blockDim.x >> 5) + (threadIdx.x >> 5); // (tbl,bag)
    const int lane = threadIdx.x & 31;
    const int tbl  = gw >> EB_LOG2_B;
    const int bag  = gw & (EB_B - 1);

    const int* off_t = offsets + tbl * EB_B;
    const int start = __ldg(&off_t[bag]);
    const int end   = (bag + 1 < EB_B) ? __ldg(&off_t[bag + 1]) : total_per_table;
    int cnt = end - start;
    if (cnt < 0) cnt = 0;

    const int* idx_t = indices + (size_t)tbl * total_per_table + start;
    const float4* __restrict__ w4 =
        (const float4*)(weights + (size_t)tbl * EB_N * EB_D);

    float4 acc = make_float4(0.f, 0.f, 0.f, 0.f);

    for (int base = 0; base < cnt; base += 32) {
        const int m = min(32, cnt - base);
        // lane j owns index (base+j); coalesced, L1-resident line
        const int myidx = (lane < m) ? __ldg(&idx_t[base + lane]) : 0;

        if (m == 20) {
            // Hot path (L=20): full unroll, ~20 independent LDG.128 in flight.
            #pragma unroll
            for (int j = 0; j < 20; j++) {
                const int r = __shfl_sync(FULLMASK, myidx, j);
                const float4 v = ldg_na_v4(&w4[r * 32 + lane]);
                acc.x += v.x; acc.y += v.y; acc.z += v.z; acc.w += v.w;
            }
        } else {
            for (int j = 0; j < m; j++) {
                const int r = __shfl_sync(FULLMASK, myidx, j);
                const float4 v = ldg_na_v4(&w4[r * 32 + lane]);
                acc.x += v.x; acc.y += v.y; acc.z += v.z; acc.w += v.w;
            }
        }
    }

    float4* __restrict__ o4 = (float4*)out;
    __stcs(&o4[(size_t)gw * 32 + lane], acc);   // evict-first: protect L2 for weights
}

extern "C" void kernel_launch(void* const* d_in, const int* in_sizes, int n_in,
                              void* d_out, int out_size)
{
    const float* weights = (const float*)d_in[0];
    const int*   indices = (const int*)d_in[1];
    const int*   offsets = (const int*)d_in[2];
    float*       out     = (float*)d_out;

    const int total_per_table = in_sizes[1] / EB_T;  // 327680

    const int warps_per_block = 8;                   // 256 threads
    const int total_warps = EB_T * EB_B;             // 131072 bags
    const int nblocks = total_warps / warps_per_block;

    merged_embeddingbag_warp_kernel<<<nblocks, warps_per_block * 32>>>(
        weights, indices, offsets, out, total_per_table);
}

// round 6
// speedup vs baseline: 1.1866x; 1.1866x over previous
#include <cuda_runtime.h>
#include <cuda_bf16.h>

// MergedEmbeddingBag: weights [T,N,D] f32, indices [T,TOTAL] i32, offsets [T,B] i32
// out [T,B,D] f32, sum pooling. T=8, N=100000, D=128, B=16384, L=20.
//
// R6 = R2 winner restored (warp-per-bag, float4 __ldg gathers, shfl-distributed
// indices, no smem/no barriers) + __stcs evict-first output store.
// The kernel runs at the chip LTS cap (~12.5 TB/s @NAT): 1.42 GB of compulsory
// SM<->L2 traffic / cap ≈ 112 µs floor. Loads stay as __ldg intrinsics so the
// compiler front-batches all 20 gathers (R5 showed asm-volatile loads destroy
// that batching: -17%).

#define EB_T 8
#define EB_N 100000
#define EB_D 128
#define EB_B 16384
#define EB_LOG2_B 14
#define FULLMASK 0xffffffffu

__global__ void __launch_bounds__(256, 4)
merged_embeddingbag_warp_kernel(const float* __restrict__ weights,
                                const int* __restrict__ indices,
                                const int* __restrict__ offsets,
                                float* __restrict__ out,
                                int total_per_table)
{
    const int gw   = blockIdx.x * (blockDim.x >> 5) + (threadIdx.x >> 5); // (tbl,bag)
    const int lane = threadIdx.x & 31;
    const int tbl  = gw >> EB_LOG2_B;
    const int bag  = gw & (EB_B - 1);

    const int* off_t = offsets + tbl * EB_B;
    const int start = __ldg(&off_t[bag]);
    const int end   = (bag + 1 < EB_B) ? __ldg(&off_t[bag + 1]) : total_per_table;
    int cnt = end - start;
    if (cnt < 0) cnt = 0;

    const int* idx_t = indices + (size_t)tbl * total_per_table + start;
    const float4* __restrict__ w4 =
        (const float4*)(weights + (size_t)tbl * EB_N * EB_D);

    float4 acc = make_float4(0.f, 0.f, 0.f, 0.f);

    for (int base = 0; base < cnt; base += 32) {
        const int m = min(32, cnt - base);
        // lane j owns index (base+j): one coalesced load, no smem, no sync
        const int myidx = (lane < m) ? __ldg(&idx_t[base + lane]) : 0;

        if (m == 20) {
            // Hot path (fixed L=20): full unroll -> ~20 independent LDG.128
            // in flight per warp (compiler-batched).
            #pragma unroll
            for (int j = 0; j < 20; j++) {
                const int r = __shfl_sync(FULLMASK, myidx, j);
                const float4 v = __ldg(&w4[r * 32 + lane]);
                acc.x += v.x; acc.y += v.y; acc.z += v.z; acc.w += v.w;
            }
        } else {
            for (int j = 0; j < m; j++) {
                const int r = __shfl_sync(FULLMASK, myidx, j);
                const float4 v = __ldg(&w4[r * 32 + lane]);
                acc.x += v.x; acc.y += v.y; acc.z += v.z; acc.w += v.w;
            }
        }
    }

    float4* __restrict__ o4 = (float4*)out;
    __stcs(&o4[(size_t)gw * 32 + lane], acc);   // evict-first: protect weight lines in L2
}

extern "C" void kernel_launch(void* const* d_in, const int* in_sizes, int n_in,
                              void* d_out, int out_size)
{
    const float* weights = (const float*)d_in[0];
    const int*   indices = (const int*)d_in[1];
    const int*   offsets = (const int*)d_in[2];
    float*       out     = (float*)d_out;

    const int total_per_table = in_sizes[1] / EB_T;  // 327680

    const int warps_per_block = 8;                   // 256 threads
    const int total_warps = EB_T * EB_B;             // 131072 bags
    const int nblocks = total_warps / warps_per_block;

    merged_embeddingbag_warp_kernel<<<nblocks, warps_per_block * 32>>>(
        weights, indices, offsets, out, total_per_table);
}